// round 3
// baseline (speedup 1.0000x reference)
#include <cuda_runtime.h>
#include <cstdint>

// Causal SDPA, tf32 tensor-core flash attention (mma.sync.m16n8k8.tf32).
// B=4, H=12, S=2048, D=64. Inputs (metadata order): keys, queries, values.
//
// CTA = 128 threads (4 warps), Q tile 128 rows (32/warp = 2 x m16), KV tile 64.
// P is kept in registers: QK accumulator feeds PV A-fragment via a key-index
// permutation applied consistently to V's B-fragment rows (no smem round-trip).

#define SEQ 2048
#define DH 64
#define QT 128
#define KT 64
#define QSTR 68
#define KSTR 68
#define VSTR 68

__device__ __forceinline__ float tf32r(float x) {
    asm("cvt.rna.tf32.f32 %0, %0;" : "+f"(x));
    return x;
}

__device__ __forceinline__ void mma_tf32(float c[4],
                                         uint32_t a0, uint32_t a1, uint32_t a2, uint32_t a3,
                                         uint32_t b0, uint32_t b1) {
    asm volatile("mma.sync.aligned.m16n8k8.row.col.f32.tf32.tf32.f32 "
                 "{%0,%1,%2,%3}, {%4,%5,%6,%7}, {%8,%9}, {%0,%1,%2,%3};"
                 : "+f"(c[0]), "+f"(c[1]), "+f"(c[2]), "+f"(c[3])
                 : "r"(a0), "r"(a1), "r"(a2), "r"(a3), "r"(b0), "r"(b1));
}

__global__ __launch_bounds__(128, 3)
void fa_tf32_kernel(const float* __restrict__ Kg_, const float* __restrict__ Qg_,
                    const float* __restrict__ Vg_, float* __restrict__ Og_)
{
    extern __shared__ float sm[];
    float* Qs = sm;                    // 128 x 68
    float* Ks = Qs + QT * QSTR;        // 64 x 68
    float* Vs = Ks + KT * KSTR;        // 64 x 68

    const int qt   = gridDim.x - 1 - blockIdx.x;   // heavy tiles first
    const int bh   = blockIdx.y;
    const int tid  = threadIdx.x;
    const int w    = tid >> 5;
    const int lane = tid & 31;
    const int lr   = lane >> 2;        // groupID 0..7
    const int lc   = lane & 3;         // threadInGroup 0..3

    const size_t base = (size_t)bh * SEQ * DH;
    const float4* Qg = (const float4*)(Qg_ + base);
    const float4* Kg = (const float4*)(Kg_ + base);
    const float4* Vg = (const float4*)(Vg_ + base);

    // ---- load Q tile (pre-scaled by 1/8, tf32 rna-rounded) ----
    #pragma unroll
    for (int i = 0; i < 16; i++) {
        int idx = tid + i * 128;
        int row = idx >> 4, c4 = idx & 15;
        float4 q = Qg[(qt * QT + row) * 16 + c4];
        q.x = tf32r(q.x * 0.125f); q.y = tf32r(q.y * 0.125f);
        q.z = tf32r(q.z * 0.125f); q.w = tf32r(q.w * 0.125f);
        *(float4*)&Qs[row * QSTR + c4 * 4] = q;
    }

    float o[2][8][4];
    float m[2][2], l[2][2];
    #pragma unroll
    for (int mb = 0; mb < 2; mb++) {
        m[mb][0] = -1e30f; m[mb][1] = -1e30f;
        l[mb][0] = 0.f;    l[mb][1] = 0.f;
        #pragma unroll
        for (int n = 0; n < 8; n++)
            #pragma unroll
            for (int j = 0; j < 4; j++) o[mb][n][j] = 0.f;
    }

    const int ktmax    = 2 * qt + 2;
    const int wrow_min = qt * QT + w * 32;
    const int wrow_max = wrow_min + 31;

    const uint32_t* Qsu = (const uint32_t*)Qs;
    const uint32_t* Ksu = (const uint32_t*)Ks;
    const uint32_t* Vsu = (const uint32_t*)Vs;

    for (int kt = 0; kt < ktmax; kt++) {
        __syncthreads();
        // ---- load K, V tiles (tf32 rna-rounded) ----
        #pragma unroll
        for (int i = 0; i < 8; i++) {
            int idx = tid + i * 128;
            int row = idx >> 4, c4 = idx & 15;
            float4 k = Kg[(kt * KT + row) * 16 + c4];
            k.x = tf32r(k.x); k.y = tf32r(k.y); k.z = tf32r(k.z); k.w = tf32r(k.w);
            *(float4*)&Ks[row * KSTR + c4 * 4] = k;
            float4 v = Vg[(kt * KT + row) * 16 + c4];
            v.x = tf32r(v.x); v.y = tf32r(v.y); v.z = tf32r(v.z); v.w = tf32r(v.w);
            *(float4*)&Vs[row * VSTR + c4 * 4] = v;
        }
        __syncthreads();

        if (kt * KT <= wrow_max) {
            const bool diag = (kt * KT + KT - 1 > wrow_min);
            #pragma unroll
            for (int mb = 0; mb < 2; mb++) {
                const int rl = w * 32 + mb * 16 + lr;   // local Q row (lo half)

                // ---- QK: S[16x64] ----
                float s[8][4];
                #pragma unroll
                for (int n = 0; n < 8; n++)
                    #pragma unroll
                    for (int j = 0; j < 4; j++) s[n][j] = 0.f;

                #pragma unroll
                for (int k = 0; k < 8; k++) {
                    uint32_t a0 = Qsu[ rl      * QSTR + k * 8 + lc];
                    uint32_t a1 = Qsu[(rl + 8) * QSTR + k * 8 + lc];
                    uint32_t a2 = Qsu[ rl      * QSTR + k * 8 + lc + 4];
                    uint32_t a3 = Qsu[(rl + 8) * QSTR + k * 8 + lc + 4];
                    #pragma unroll
                    for (int n = 0; n < 8; n++) {
                        uint32_t b0 = Ksu[(n * 8 + lr) * KSTR + k * 8 + lc];
                        uint32_t b1 = Ksu[(n * 8 + lr) * KSTR + k * 8 + lc + 4];
                        mma_tf32(s[n], a0, a1, a2, a3, b0, b1);
                    }
                }

                // ---- causal mask (near-diagonal tiles only) ----
                if (diag) {
                    int qlo = qt * QT + rl;
                    int qhi = qlo + 8;
                    #pragma unroll
                    for (int n = 0; n < 8; n++) {
                        int key = kt * KT + n * 8 + 2 * lc;
                        if (key     > qlo) s[n][0] = -1e30f;
                        if (key + 1 > qlo) s[n][1] = -1e30f;
                        if (key     > qhi) s[n][2] = -1e30f;
                        if (key + 1 > qhi) s[n][3] = -1e30f;
                    }
                }

                // ---- online softmax (exp in place: s -> p) ----
                float rmx0 = -1e30f, rmx1 = -1e30f;
                #pragma unroll
                for (int n = 0; n < 8; n++) {
                    rmx0 = fmaxf(rmx0, fmaxf(s[n][0], s[n][1]));
                    rmx1 = fmaxf(rmx1, fmaxf(s[n][2], s[n][3]));
                }
                rmx0 = fmaxf(rmx0, __shfl_xor_sync(0xffffffffu, rmx0, 1));
                rmx0 = fmaxf(rmx0, __shfl_xor_sync(0xffffffffu, rmx0, 2));
                rmx1 = fmaxf(rmx1, __shfl_xor_sync(0xffffffffu, rmx1, 1));
                rmx1 = fmaxf(rmx1, __shfl_xor_sync(0xffffffffu, rmx1, 2));

                float mn0 = fmaxf(m[mb][0], rmx0);
                float mn1 = fmaxf(m[mb][1], rmx1);
                float corr0 = __expf(m[mb][0] - mn0);
                float corr1 = __expf(m[mb][1] - mn1);
                m[mb][0] = mn0; m[mb][1] = mn1;

                float ps0 = 0.f, ps1 = 0.f;
                #pragma unroll
                for (int n = 0; n < 8; n++) {
                    s[n][0] = __expf(s[n][0] - mn0);
                    s[n][1] = __expf(s[n][1] - mn0);
                    s[n][2] = __expf(s[n][2] - mn1);
                    s[n][3] = __expf(s[n][3] - mn1);
                    ps0 += s[n][0] + s[n][1];
                    ps1 += s[n][2] + s[n][3];
                }
                ps0 += __shfl_xor_sync(0xffffffffu, ps0, 1);
                ps0 += __shfl_xor_sync(0xffffffffu, ps0, 2);
                ps1 += __shfl_xor_sync(0xffffffffu, ps1, 1);
                ps1 += __shfl_xor_sync(0xffffffffu, ps1, 2);
                l[mb][0] = l[mb][0] * corr0 + ps0;
                l[mb][1] = l[mb][1] * corr1 + ps1;

                #pragma unroll
                for (int n = 0; n < 8; n++) {
                    o[mb][n][0] *= corr0; o[mb][n][1] *= corr0;
                    o[mb][n][2] *= corr1; o[mb][n][3] *= corr1;
                }

                // ---- PV: O += P * V, P in registers via key permutation ----
                // A-frag col c maps to key pi(c): pi(c)=2c (c<4), 2(c-4)+1 (c>=4)
                // => a = {s[k][0], s[k][2], s[k][1], s[k][3]},
                //    b0 = V[key k*8+2lc], b1 = V[key k*8+2lc+1]
                #pragma unroll
                for (int k = 0; k < 8; k++) {
                    uint32_t a0 = __float_as_uint(tf32r(s[k][0]));
                    uint32_t a1 = __float_as_uint(tf32r(s[k][2]));
                    uint32_t a2 = __float_as_uint(tf32r(s[k][1]));
                    uint32_t a3 = __float_as_uint(tf32r(s[k][3]));
                    #pragma unroll
                    for (int n = 0; n < 8; n++) {
                        uint32_t b0 = Vsu[(k * 8 + 2 * lc)     * VSTR + n * 8 + lr];
                        uint32_t b1 = Vsu[(k * 8 + 2 * lc + 1) * VSTR + n * 8 + lr];
                        mma_tf32(o[mb][n], a0, a1, a2, a3, b0, b1);
                    }
                }
            }
        }
    }

    // ---- epilogue: normalize + store ----
    float2* Og = (float2*)(Og_ + base);
    #pragma unroll
    for (int mb = 0; mb < 2; mb++) {
        float inv0 = 1.0f / l[mb][0];
        float inv1 = 1.0f / l[mb][1];
        int grow = qt * QT + w * 32 + mb * 16 + lr;
        #pragma unroll
        for (int n = 0; n < 8; n++) {
            Og[ grow      * 32 + n * 4 + lc] = make_float2(o[mb][n][0] * inv0, o[mb][n][1] * inv0);
            Og[(grow + 8) * 32 + n * 4 + lc] = make_float2(o[mb][n][2] * inv1, o[mb][n][3] * inv1);
        }
    }
}

extern "C" void kernel_launch(void* const* d_in, const int* in_sizes, int n_in,
                              void* d_out, int out_size) {
    const float* K = (const float*)d_in[0];
    const float* Q = (const float*)d_in[1];
    const float* V = (const float*)d_in[2];
    float* O = (float*)d_out;

    size_t smem = (size_t)(QT * QSTR + KT * KSTR + KT * VSTR) * sizeof(float);
    cudaFuncSetAttribute(fa_tf32_kernel,
                         cudaFuncAttributeMaxDynamicSharedMemorySize, (int)smem);

    dim3 grid(SEQ / QT, 48);
    fa_tf32_kernel<<<grid, 128, (int)smem>>>(K, Q, V, O);
}

// round 4
// speedup vs baseline: 1.3704x; 1.3704x over previous
#include <cuda_runtime.h>
#include <cstdint>

// Causal SDPA, tf32 tensor-core flash attention (mma.sync.m16n8k8.tf32).
// B=4, H=12, S=2048, D=64. Inputs (metadata order): keys, queries, values.
//
// CTA = 128 threads (4 warps), Q tile 128 rows (32/warp = 2 x m16), KV tile 64.
// P kept in registers (QK accumulator feeds PV A-fragment via key permutation).
// K/V double-buffered in smem via cp.async; tf32 rna rounding applied at
// fragment-load time (identical numerics to rounding before the smem copy).

#define SEQ 2048
#define DH 64
#define QT 128
#define KT 64
#define QSTR 68
#define KSTR 68
#define VSTR 68
#define KVSTAGE (KT * KSTR)      // floats per K (or V) stage

__device__ __forceinline__ float tf32r(float x) {
    asm("cvt.rna.tf32.f32 %0, %0;" : "+f"(x));
    return x;
}
__device__ __forceinline__ uint32_t tf32u(float x) {
    asm("cvt.rna.tf32.f32 %0, %0;" : "+f"(x));
    return __float_as_uint(x);
}

__device__ __forceinline__ void mma_tf32(float c[4],
                                         uint32_t a0, uint32_t a1, uint32_t a2, uint32_t a3,
                                         uint32_t b0, uint32_t b1) {
    asm volatile("mma.sync.aligned.m16n8k8.row.col.f32.tf32.tf32.f32 "
                 "{%0,%1,%2,%3}, {%4,%5,%6,%7}, {%8,%9}, {%0,%1,%2,%3};"
                 : "+f"(c[0]), "+f"(c[1]), "+f"(c[2]), "+f"(c[3])
                 : "r"(a0), "r"(a1), "r"(a2), "r"(a3), "r"(b0), "r"(b1));
}

__device__ __forceinline__ void cp16(uint32_t saddr, const void* gaddr) {
    asm volatile("cp.async.cg.shared.global [%0], [%1], 16;" :: "r"(saddr), "l"(gaddr));
}
__device__ __forceinline__ void cp_commit() {
    asm volatile("cp.async.commit_group;");
}
template <int N>
__device__ __forceinline__ void cp_wait() {
    asm volatile("cp.async.wait_group %0;" :: "n"(N));
}

__global__ __launch_bounds__(128, 2)
void fa_tf32_kernel(const float* __restrict__ Kg_, const float* __restrict__ Qg_,
                    const float* __restrict__ Vg_, float* __restrict__ Og_)
{
    extern __shared__ float sm[];
    float* Qs = sm;                          // 128 x 68
    float* Kb = Qs + QT * QSTR;              // 2 x (64 x 68)
    float* Vb = Kb + 2 * KVSTAGE;            // 2 x (64 x 68)

    const int qt   = gridDim.x - 1 - blockIdx.x;   // heavy tiles first
    const int bh   = blockIdx.y;
    const int tid  = threadIdx.x;
    const int w    = tid >> 5;
    const int lane = tid & 31;
    const int lr   = lane >> 2;
    const int lc   = lane & 3;

    const size_t base = (size_t)bh * SEQ * DH;
    const float4* Qg = (const float4*)(Qg_ + base);
    const float4* Kg = (const float4*)(Kg_ + base);
    const float4* Vg = (const float4*)(Vg_ + base);

    // per-thread copy slot: row/col for the 8 float4s it moves per tile
    const int crow = tid >> 4;               // 0..7 base row
    const int cc4  = tid & 15;               // float4 col 0..15

    const uint32_t KbU = (uint32_t)__cvta_generic_to_shared(Kb);
    const uint32_t VbU = (uint32_t)__cvta_generic_to_shared(Vb);

    // ---- prologue: issue cp.async for KV tile 0 into stage 0 ----
    {
        #pragma unroll
        for (int i = 0; i < 8; i++) {
            int row = crow + i * 8;
            uint32_t soff = (uint32_t)(row * KSTR + cc4 * 4) * 4u;
            cp16(KbU + soff, Kg + (size_t)row * 16 + cc4);
            cp16(VbU + soff, Vg + (size_t)row * 16 + cc4);
        }
        cp_commit();
    }

    // ---- load Q tile (pre-scaled by 1/8, tf32 rna-rounded) ----
    #pragma unroll
    for (int i = 0; i < 16; i++) {
        int idx = tid + i * 128;
        int row = idx >> 4, c4 = idx & 15;
        float4 q = Qg[(qt * QT + row) * 16 + c4];
        q.x = tf32r(q.x * 0.125f); q.y = tf32r(q.y * 0.125f);
        q.z = tf32r(q.z * 0.125f); q.w = tf32r(q.w * 0.125f);
        *(float4*)&Qs[row * QSTR + c4 * 4] = q;
    }

    float o[2][8][4];
    float m[2][2], l[2][2];
    #pragma unroll
    for (int mb = 0; mb < 2; mb++) {
        m[mb][0] = -1e30f; m[mb][1] = -1e30f;
        l[mb][0] = 0.f;    l[mb][1] = 0.f;
        #pragma unroll
        for (int n = 0; n < 8; n++)
            #pragma unroll
            for (int j = 0; j < 4; j++) o[mb][n][j] = 0.f;
    }

    const int ktmax    = 2 * qt + 2;
    const int wrow_min = qt * QT + w * 32;
    const int wrow_max = wrow_min + 31;

    const uint32_t* Qsu = (const uint32_t*)Qs;

    for (int kt = 0; kt < ktmax; kt++) {
        const int cur = kt & 1;
        // all reads of stage cur^1 (iteration kt-1) are complete after this:
        __syncthreads();

        if (kt + 1 < ktmax) {
            const int nxt = cur ^ 1;
            #pragma unroll
            for (int i = 0; i < 8; i++) {
                int row = crow + i * 8;
                uint32_t soff = (uint32_t)(nxt * KVSTAGE + row * KSTR + cc4 * 4) * 4u;
                cp16(KbU + soff, Kg + (size_t)((kt + 1) * KT + row) * 16 + cc4);
                cp16(VbU + soff, Vg + (size_t)((kt + 1) * KT + row) * 16 + cc4);
            }
            cp_commit();
            cp_wait<1>();     // tile kt's group done; kt+1 may still be in flight
        } else {
            cp_wait<0>();
        }
        __syncthreads();

        const uint32_t* Ksu = (const uint32_t*)(Kb + cur * KVSTAGE);
        const uint32_t* Vsu = (const uint32_t*)(Vb + cur * KVSTAGE);

        if (kt * KT <= wrow_max) {
            const bool diag = (kt * KT + KT - 1 > wrow_min);
            #pragma unroll
            for (int mb = 0; mb < 2; mb++) {
                const int rl = w * 32 + mb * 16 + lr;

                // ---- QK: S[16x64] ----
                float s[8][4];
                #pragma unroll
                for (int n = 0; n < 8; n++)
                    #pragma unroll
                    for (int j = 0; j < 4; j++) s[n][j] = 0.f;

                #pragma unroll
                for (int k = 0; k < 8; k++) {
                    uint32_t a0 = Qsu[ rl      * QSTR + k * 8 + lc];
                    uint32_t a1 = Qsu[(rl + 8) * QSTR + k * 8 + lc];
                    uint32_t a2 = Qsu[ rl      * QSTR + k * 8 + lc + 4];
                    uint32_t a3 = Qsu[(rl + 8) * QSTR + k * 8 + lc + 4];
                    #pragma unroll
                    for (int n = 0; n < 8; n++) {
                        uint32_t b0 = tf32u(__uint_as_float(Ksu[(n * 8 + lr) * KSTR + k * 8 + lc]));
                        uint32_t b1 = tf32u(__uint_as_float(Ksu[(n * 8 + lr) * KSTR + k * 8 + lc + 4]));
                        mma_tf32(s[n], a0, a1, a2, a3, b0, b1);
                    }
                }

                // ---- causal mask ----
                if (diag) {
                    int qlo = qt * QT + rl;
                    int qhi = qlo + 8;
                    #pragma unroll
                    for (int n = 0; n < 8; n++) {
                        int key = kt * KT + n * 8 + 2 * lc;
                        if (key     > qlo) s[n][0] = -1e30f;
                        if (key + 1 > qlo) s[n][1] = -1e30f;
                        if (key     > qhi) s[n][2] = -1e30f;
                        if (key + 1 > qhi) s[n][3] = -1e30f;
                    }
                }

                // ---- online softmax ----
                float rmx0 = -1e30f, rmx1 = -1e30f;
                #pragma unroll
                for (int n = 0; n < 8; n++) {
                    rmx0 = fmaxf(rmx0, fmaxf(s[n][0], s[n][1]));
                    rmx1 = fmaxf(rmx1, fmaxf(s[n][2], s[n][3]));
                }
                rmx0 = fmaxf(rmx0, __shfl_xor_sync(0xffffffffu, rmx0, 1));
                rmx0 = fmaxf(rmx0, __shfl_xor_sync(0xffffffffu, rmx0, 2));
                rmx1 = fmaxf(rmx1, __shfl_xor_sync(0xffffffffu, rmx1, 1));
                rmx1 = fmaxf(rmx1, __shfl_xor_sync(0xffffffffu, rmx1, 2));

                float mn0 = fmaxf(m[mb][0], rmx0);
                float mn1 = fmaxf(m[mb][1], rmx1);
                float corr0 = __expf(m[mb][0] - mn0);
                float corr1 = __expf(m[mb][1] - mn1);
                m[mb][0] = mn0; m[mb][1] = mn1;

                float ps0 = 0.f, ps1 = 0.f;
                #pragma unroll
                for (int n = 0; n < 8; n++) {
                    s[n][0] = __expf(s[n][0] - mn0);
                    s[n][1] = __expf(s[n][1] - mn0);
                    s[n][2] = __expf(s[n][2] - mn1);
                    s[n][3] = __expf(s[n][3] - mn1);
                    ps0 += s[n][0] + s[n][1];
                    ps1 += s[n][2] + s[n][3];
                }
                ps0 += __shfl_xor_sync(0xffffffffu, ps0, 1);
                ps0 += __shfl_xor_sync(0xffffffffu, ps0, 2);
                ps1 += __shfl_xor_sync(0xffffffffu, ps1, 1);
                ps1 += __shfl_xor_sync(0xffffffffu, ps1, 2);
                l[mb][0] = l[mb][0] * corr0 + ps0;
                l[mb][1] = l[mb][1] * corr1 + ps1;

                #pragma unroll
                for (int n = 0; n < 8; n++) {
                    o[mb][n][0] *= corr0; o[mb][n][1] *= corr0;
                    o[mb][n][2] *= corr1; o[mb][n][3] *= corr1;
                }

                // ---- PV: O += P * V (P in regs, key permutation pi(c)) ----
                #pragma unroll
                for (int k = 0; k < 8; k++) {
                    uint32_t a0 = tf32u(s[k][0]);
                    uint32_t a1 = tf32u(s[k][2]);
                    uint32_t a2 = tf32u(s[k][1]);
                    uint32_t a3 = tf32u(s[k][3]);
                    #pragma unroll
                    for (int n = 0; n < 8; n++) {
                        uint32_t b0 = tf32u(__uint_as_float(Vsu[(k * 8 + 2 * lc)     * VSTR + n * 8 + lr]));
                        uint32_t b1 = tf32u(__uint_as_float(Vsu[(k * 8 + 2 * lc + 1) * VSTR + n * 8 + lr]));
                        mma_tf32(o[mb][n], a0, a1, a2, a3, b0, b1);
                    }
                }
            }
        }
    }

    // ---- epilogue: normalize + store ----
    float2* Og = (float2*)(Og_ + base);
    #pragma unroll
    for (int mb = 0; mb < 2; mb++) {
        float inv0 = 1.0f / l[mb][0];
        float inv1 = 1.0f / l[mb][1];
        int grow = qt * QT + w * 32 + mb * 16 + lr;
        #pragma unroll
        for (int n = 0; n < 8; n++) {
            Og[ grow      * 32 + n * 4 + lc] = make_float2(o[mb][n][0] * inv0, o[mb][n][1] * inv0);
            Og[(grow + 8) * 32 + n * 4 + lc] = make_float2(o[mb][n][2] * inv1, o[mb][n][3] * inv1);
        }
    }
}

extern "C" void kernel_launch(void* const* d_in, const int* in_sizes, int n_in,
                              void* d_out, int out_size) {
    const float* K = (const float*)d_in[0];
    const float* Q = (const float*)d_in[1];
    const float* V = (const float*)d_in[2];
    float* O = (float*)d_out;

    size_t smem = (size_t)(QT * QSTR + 4 * KVSTAGE) * sizeof(float);  // 104448 B
    cudaFuncSetAttribute(fa_tf32_kernel,
                         cudaFuncAttributeMaxDynamicSharedMemorySize, (int)smem);

    dim3 grid(SEQ / QT, 48);
    fa_tf32_kernel<<<grid, 128, (int)smem>>>(K, Q, V, O);
}

// round 5
// speedup vs baseline: 1.4264x; 1.0409x over previous
#include <cuda_runtime.h>
#include <cstdint>

// Causal SDPA, tf32 tensor-core flash attention (mma.sync.m16n8k8.tf32).
// B=4, H=12, S=2048, D=64. Inputs (metadata order): keys, queries, values.
//
// CTA = 128 threads (4 warps), Q tile 128 rows (32/warp = 2 x m16), KV tile 64.
// P kept in registers (QK accumulator feeds PV A-fragment via key permutation).
// K/V double-buffered via cp.async; a single in-smem pass converts each tile
// to tf32 (rna) once, so mainloop fragment loads are plain LDS.

#define SEQ 2048
#define DH 64
#define QT 128
#define KT 64
#define QSTR 68
#define KSTR 68
#define VSTR 68
#define KVSTAGE (KT * KSTR)

__device__ __forceinline__ float tf32r(float x) {
    asm("cvt.rna.tf32.f32 %0, %0;" : "+f"(x));
    return x;
}
__device__ __forceinline__ uint32_t tf32u(float x) {
    asm("cvt.rna.tf32.f32 %0, %0;" : "+f"(x));
    return __float_as_uint(x);
}

__device__ __forceinline__ void mma_tf32(float c[4],
                                         uint32_t a0, uint32_t a1, uint32_t a2, uint32_t a3,
                                         uint32_t b0, uint32_t b1) {
    asm volatile("mma.sync.aligned.m16n8k8.row.col.f32.tf32.tf32.f32 "
                 "{%0,%1,%2,%3}, {%4,%5,%6,%7}, {%8,%9}, {%0,%1,%2,%3};"
                 : "+f"(c[0]), "+f"(c[1]), "+f"(c[2]), "+f"(c[3])
                 : "r"(a0), "r"(a1), "r"(a2), "r"(a3), "r"(b0), "r"(b1));
}

__device__ __forceinline__ void cp16(uint32_t saddr, const void* gaddr) {
    asm volatile("cp.async.cg.shared.global [%0], [%1], 16;" :: "r"(saddr), "l"(gaddr));
}
__device__ __forceinline__ void cp_commit() {
    asm volatile("cp.async.commit_group;");
}
template <int N>
__device__ __forceinline__ void cp_wait() {
    asm volatile("cp.async.wait_group %0;" :: "n"(N));
}

__global__ __launch_bounds__(128, 2)
void fa_tf32_kernel(const float* __restrict__ Kg_, const float* __restrict__ Qg_,
                    const float* __restrict__ Vg_, float* __restrict__ Og_)
{
    extern __shared__ float sm[];
    float* Qs = sm;                          // 128 x 68
    float* Kb = Qs + QT * QSTR;              // 2 stages x (64 x 68)
    float* Vb = Kb + 2 * KVSTAGE;            // 2 stages x (64 x 68)

    const int qt   = gridDim.x - 1 - blockIdx.x;   // heavy tiles first
    const int bh   = blockIdx.y;
    const int tid  = threadIdx.x;
    const int w    = tid >> 5;
    const int lane = tid & 31;
    const int lr   = lane >> 2;
    const int lc   = lane & 3;

    const size_t base = (size_t)bh * SEQ * DH;
    const float4* Qg = (const float4*)(Qg_ + base);
    const float4* Kg = (const float4*)(Kg_ + base);
    const float4* Vg = (const float4*)(Vg_ + base);

    const int crow = tid >> 4;               // copy-slot base row (0..7)
    const int cc4  = tid & 15;               // copy-slot float4 col

    const uint32_t KbU = (uint32_t)__cvta_generic_to_shared(Kb);
    const uint32_t VbU = (uint32_t)__cvta_generic_to_shared(Vb);

    // ---- prologue: cp.async KV tile 0 into stage 0 ----
    #pragma unroll
    for (int i = 0; i < 8; i++) {
        int row = crow + i * 8;
        uint32_t soff = (uint32_t)(row * KSTR + cc4 * 4) * 4u;
        cp16(KbU + soff, Kg + (size_t)row * 16 + cc4);
        cp16(VbU + soff, Vg + (size_t)row * 16 + cc4);
    }
    cp_commit();

    // ---- load Q tile (pre-scaled by 1/8, tf32 rna) ----
    #pragma unroll
    for (int i = 0; i < 16; i++) {
        int idx = tid + i * 128;
        int row = idx >> 4, c4 = idx & 15;
        float4 q = Qg[(qt * QT + row) * 16 + c4];
        q.x = tf32r(q.x * 0.125f); q.y = tf32r(q.y * 0.125f);
        q.z = tf32r(q.z * 0.125f); q.w = tf32r(q.w * 0.125f);
        *(float4*)&Qs[row * QSTR + c4 * 4] = q;
    }

    float o[2][8][4];
    float m[2][2], l[2][2];
    #pragma unroll
    for (int mb = 0; mb < 2; mb++) {
        m[mb][0] = -1e30f; m[mb][1] = -1e30f;
        l[mb][0] = 0.f;    l[mb][1] = 0.f;
        #pragma unroll
        for (int n = 0; n < 8; n++)
            #pragma unroll
            for (int j = 0; j < 4; j++) o[mb][n][j] = 0.f;
    }

    const int ktmax    = 2 * qt + 2;
    const int wrow_min = qt * QT + w * 32;
    const int wrow_max = wrow_min + 31;

    const uint32_t* Qsu = (const uint32_t*)Qs;

    for (int kt = 0; kt < ktmax; kt++) {
        const int cur = kt & 1;
        __syncthreads();    // stage cur^1 reads from iteration kt-1 complete

        if (kt + 1 < ktmax) {
            const int nxt = cur ^ 1;
            #pragma unroll
            for (int i = 0; i < 8; i++) {
                int row = crow + i * 8;
                uint32_t soff = (uint32_t)(nxt * KVSTAGE + row * KSTR + cc4 * 4) * 4u;
                cp16(KbU + soff, Kg + (size_t)((kt + 1) * KT + row) * 16 + cc4);
                cp16(VbU + soff, Vg + (size_t)((kt + 1) * KT + row) * 16 + cc4);
            }
            cp_commit();
            cp_wait<1>();   // tile kt's data has arrived
        } else {
            cp_wait<0>();
        }
        __syncthreads();

        float* Kc = Kb + cur * KVSTAGE;
        float* Vc = Vb + cur * KVSTAGE;

        // ---- one-shot tf32 (rna) conversion pass, in place ----
        #pragma unroll
        for (int i = 0; i < 8; i++) {
            int idx = tid + i * 128;          // 0..1023 float4 slots
            int row = idx >> 4, c4 = idx & 15;
            float4* kp = (float4*)&Kc[row * KSTR + c4 * 4];
            float4 kx = *kp;
            kx.x = tf32r(kx.x); kx.y = tf32r(kx.y); kx.z = tf32r(kx.z); kx.w = tf32r(kx.w);
            *kp = kx;
            float4* vp = (float4*)&Vc[row * VSTR + c4 * 4];
            float4 vx = *vp;
            vx.x = tf32r(vx.x); vx.y = tf32r(vx.y); vx.z = tf32r(vx.z); vx.w = tf32r(vx.w);
            *vp = vx;
        }
        __syncthreads();

        const uint32_t* Ksu = (const uint32_t*)Kc;
        const uint32_t* Vsu = (const uint32_t*)Vc;

        if (kt * KT <= wrow_max) {
            const bool diag = (kt * KT + KT - 1 > wrow_min);
            #pragma unroll
            for (int mb = 0; mb < 2; mb++) {
                const int rl = w * 32 + mb * 16 + lr;

                // ---- QK: S[16x64] ----
                float s[8][4];
                #pragma unroll
                for (int n = 0; n < 8; n++)
                    #pragma unroll
                    for (int j = 0; j < 4; j++) s[n][j] = 0.f;

                #pragma unroll
                for (int k = 0; k < 8; k++) {
                    uint32_t a0 = Qsu[ rl      * QSTR + k * 8 + lc];
                    uint32_t a1 = Qsu[(rl + 8) * QSTR + k * 8 + lc];
                    uint32_t a2 = Qsu[ rl      * QSTR + k * 8 + lc + 4];
                    uint32_t a3 = Qsu[(rl + 8) * QSTR + k * 8 + lc + 4];
                    #pragma unroll
                    for (int n = 0; n < 8; n++) {
                        uint32_t b0 = Ksu[(n * 8 + lr) * KSTR + k * 8 + lc];
                        uint32_t b1 = Ksu[(n * 8 + lr) * KSTR + k * 8 + lc + 4];
                        mma_tf32(s[n], a0, a1, a2, a3, b0, b1);
                    }
                }

                // ---- causal mask (near-diagonal tiles only) ----
                if (diag) {
                    int qlo = qt * QT + rl;
                    int qhi = qlo + 8;
                    #pragma unroll
                    for (int n = 0; n < 8; n++) {
                        int key = kt * KT + n * 8 + 2 * lc;
                        if (key     > qlo) s[n][0] = -1e30f;
                        if (key + 1 > qlo) s[n][1] = -1e30f;
                        if (key     > qhi) s[n][2] = -1e30f;
                        if (key + 1 > qhi) s[n][3] = -1e30f;
                    }
                }

                // ---- online softmax ----
                float rmx0 = -1e30f, rmx1 = -1e30f;
                #pragma unroll
                for (int n = 0; n < 8; n++) {
                    rmx0 = fmaxf(rmx0, fmaxf(s[n][0], s[n][1]));
                    rmx1 = fmaxf(rmx1, fmaxf(s[n][2], s[n][3]));
                }
                rmx0 = fmaxf(rmx0, __shfl_xor_sync(0xffffffffu, rmx0, 1));
                rmx0 = fmaxf(rmx0, __shfl_xor_sync(0xffffffffu, rmx0, 2));
                rmx1 = fmaxf(rmx1, __shfl_xor_sync(0xffffffffu, rmx1, 1));
                rmx1 = fmaxf(rmx1, __shfl_xor_sync(0xffffffffu, rmx1, 2));

                float mn0 = fmaxf(m[mb][0], rmx0);
                float mn1 = fmaxf(m[mb][1], rmx1);
                float corr0 = __expf(m[mb][0] - mn0);
                float corr1 = __expf(m[mb][1] - mn1);
                m[mb][0] = mn0; m[mb][1] = mn1;

                float ps0 = 0.f, ps1 = 0.f;
                #pragma unroll
                for (int n = 0; n < 8; n++) {
                    s[n][0] = __expf(s[n][0] - mn0);
                    s[n][1] = __expf(s[n][1] - mn0);
                    s[n][2] = __expf(s[n][2] - mn1);
                    s[n][3] = __expf(s[n][3] - mn1);
                    ps0 += s[n][0] + s[n][1];
                    ps1 += s[n][2] + s[n][3];
                }
                ps0 += __shfl_xor_sync(0xffffffffu, ps0, 1);
                ps0 += __shfl_xor_sync(0xffffffffu, ps0, 2);
                ps1 += __shfl_xor_sync(0xffffffffu, ps1, 1);
                ps1 += __shfl_xor_sync(0xffffffffu, ps1, 2);
                l[mb][0] = l[mb][0] * corr0 + ps0;
                l[mb][1] = l[mb][1] * corr1 + ps1;

                #pragma unroll
                for (int n = 0; n < 8; n++) {
                    o[mb][n][0] *= corr0; o[mb][n][1] *= corr0;
                    o[mb][n][2] *= corr1; o[mb][n][3] *= corr1;
                }

                // ---- PV: O += P * V (P in regs via key permutation) ----
                #pragma unroll
                for (int k = 0; k < 8; k++) {
                    uint32_t a0 = tf32u(s[k][0]);
                    uint32_t a1 = tf32u(s[k][2]);
                    uint32_t a2 = tf32u(s[k][1]);
                    uint32_t a3 = tf32u(s[k][3]);
                    #pragma unroll
                    for (int n = 0; n < 8; n++) {
                        uint32_t b0 = Vsu[(k * 8 + 2 * lc)     * VSTR + n * 8 + lr];
                        uint32_t b1 = Vsu[(k * 8 + 2 * lc + 1) * VSTR + n * 8 + lr];
                        mma_tf32(o[mb][n], a0, a1, a2, a3, b0, b1);
                    }
                }
            }
        }
    }

    // ---- epilogue: normalize + store ----
    float2* Og = (float2*)(Og_ + base);
    #pragma unroll
    for (int mb = 0; mb < 2; mb++) {
        float inv0 = 1.0f / l[mb][0];
        float inv1 = 1.0f / l[mb][1];
        int grow = qt * QT + w * 32 + mb * 16 + lr;
        #pragma unroll
        for (int n = 0; n < 8; n++) {
            Og[ grow      * 32 + n * 4 + lc] = make_float2(o[mb][n][0] * inv0, o[mb][n][1] * inv0);
            Og[(grow + 8) * 32 + n * 4 + lc] = make_float2(o[mb][n][2] * inv1, o[mb][n][3] * inv1);
        }
    }
}

extern "C" void kernel_launch(void* const* d_in, const int* in_sizes, int n_in,
                              void* d_out, int out_size) {
    const float* K = (const float*)d_in[0];
    const float* Q = (const float*)d_in[1];
    const float* V = (const float*)d_in[2];
    float* O = (float*)d_out;

    size_t smem = (size_t)(QT * QSTR + 4 * KVSTAGE) * sizeof(float);  // 104448 B
    cudaFuncSetAttribute(fa_tf32_kernel,
                         cudaFuncAttributeMaxDynamicSharedMemorySize, (int)smem);

    dim3 grid(SEQ / QT, 48);
    fa_tf32_kernel<<<grid, 128, (int)smem>>>(K, Q, V, O);
}

// round 6
// speedup vs baseline: 1.9538x; 1.3697x over previous
#include <cuda_runtime.h>
#include <cstdint>

// Causal SDPA, tf32 tensor-core flash attention (mma.sync.m16n8k8.tf32).
// B=4, H=12, S=2048, D=64. Inputs (metadata order): keys, queries, values.
//
// CTA = 128 threads (4 warps), Q tile 64 rows (16/warp = 1 x m16), KV tile 64.
// Small per-thread state (o=32, s=32 regs) -> high occupancy (3-4 CTAs/SM).
// P kept in registers: QK accumulator feeds PV A-fragment via key permutation
// pi(c) = 2c (c<4), 2(c-4)+1 (c>=4), applied to V's B-fragment rows.

#define SEQ 2048
#define DH 64
#define QT 64
#define KT 64
#define QSTR 68
#define KSTR 68
#define VSTR 68

__device__ __forceinline__ float tf32r(float x) {
    asm("cvt.rna.tf32.f32 %0, %0;" : "+f"(x));
    return x;
}
__device__ __forceinline__ uint32_t tf32u(float x) {
    asm("cvt.rna.tf32.f32 %0, %0;" : "+f"(x));
    return __float_as_uint(x);
}

__device__ __forceinline__ void mma_tf32(float c[4],
                                         uint32_t a0, uint32_t a1, uint32_t a2, uint32_t a3,
                                         uint32_t b0, uint32_t b1) {
    asm volatile("mma.sync.aligned.m16n8k8.row.col.f32.tf32.tf32.f32 "
                 "{%0,%1,%2,%3}, {%4,%5,%6,%7}, {%8,%9}, {%0,%1,%2,%3};"
                 : "+f"(c[0]), "+f"(c[1]), "+f"(c[2]), "+f"(c[3])
                 : "r"(a0), "r"(a1), "r"(a2), "r"(a3), "r"(b0), "r"(b1));
}

__global__ __launch_bounds__(128, 3)
void fa_tf32_kernel(const float* __restrict__ Kg_, const float* __restrict__ Qg_,
                    const float* __restrict__ Vg_, float* __restrict__ Og_)
{
    extern __shared__ float sm[];
    float* Qs = sm;                    // 64 x 68
    float* Ks = Qs + QT * QSTR;        // 64 x 68
    float* Vs = Ks + KT * KSTR;        // 64 x 68

    const int qt   = gridDim.x - 1 - blockIdx.x;   // heavy tiles first
    const int bh   = blockIdx.y;
    const int tid  = threadIdx.x;
    const int w    = tid >> 5;
    const int lane = tid & 31;
    const int lr   = lane >> 2;        // 0..7
    const int lc   = lane & 3;         // 0..3

    const size_t base = (size_t)bh * SEQ * DH;
    const float4* Qg = (const float4*)(Qg_ + base);
    const float4* Kg = (const float4*)(Kg_ + base);
    const float4* Vg = (const float4*)(Vg_ + base);

    // ---- load Q tile (pre-scaled by 1/8, tf32 rna) ----
    #pragma unroll
    for (int i = 0; i < 8; i++) {
        int idx = tid + i * 128;           // 0..1023
        int row = idx >> 4, c4 = idx & 15;
        float4 q = Qg[(qt * QT + row) * 16 + c4];
        q.x = tf32r(q.x * 0.125f); q.y = tf32r(q.y * 0.125f);
        q.z = tf32r(q.z * 0.125f); q.w = tf32r(q.w * 0.125f);
        *(float4*)&Qs[row * QSTR + c4 * 4] = q;
    }

    float o[8][4];
    float m0 = -1e30f, m1 = -1e30f, l0 = 0.f, l1 = 0.f;
    #pragma unroll
    for (int n = 0; n < 8; n++)
        #pragma unroll
        for (int j = 0; j < 4; j++) o[n][j] = 0.f;

    const int rl = w * 16 + lr;            // warp-local Q row (lo half)

    const uint32_t* Qsu = (const uint32_t*)Qs;
    const uint32_t* Ksu = (const uint32_t*)Ks;
    const uint32_t* Vsu = (const uint32_t*)Vs;

    const int ktmax = qt + 1;

    for (int kt = 0; kt < ktmax; kt++) {
        __syncthreads();                   // prior tile's K/V reads done
        // ---- load K, V tiles (tf32 rna) ----
        #pragma unroll
        for (int i = 0; i < 8; i++) {
            int idx = tid + i * 128;
            int row = idx >> 4, c4 = idx & 15;
            float4 k = Kg[(kt * KT + row) * 16 + c4];
            k.x = tf32r(k.x); k.y = tf32r(k.y); k.z = tf32r(k.z); k.w = tf32r(k.w);
            *(float4*)&Ks[row * KSTR + c4 * 4] = k;
            float4 v = Vg[(kt * KT + row) * 16 + c4];
            v.x = tf32r(v.x); v.y = tf32r(v.y); v.z = tf32r(v.z); v.w = tf32r(v.w);
            *(float4*)&Vs[row * VSTR + c4 * 4] = v;
        }
        __syncthreads();

        // ---- QK: S[16x64] ----
        float s[8][4];
        #pragma unroll
        for (int n = 0; n < 8; n++)
            #pragma unroll
            for (int j = 0; j < 4; j++) s[n][j] = 0.f;

        #pragma unroll
        for (int k = 0; k < 8; k++) {
            uint32_t a0 = Qsu[ rl      * QSTR + k * 8 + lc];
            uint32_t a1 = Qsu[(rl + 8) * QSTR + k * 8 + lc];
            uint32_t a2 = Qsu[ rl      * QSTR + k * 8 + lc + 4];
            uint32_t a3 = Qsu[(rl + 8) * QSTR + k * 8 + lc + 4];
            #pragma unroll
            for (int n = 0; n < 8; n++) {
                uint32_t b0 = Ksu[(n * 8 + lr) * KSTR + k * 8 + lc];
                uint32_t b1 = Ksu[(n * 8 + lr) * KSTR + k * 8 + lc + 4];
                mma_tf32(s[n], a0, a1, a2, a3, b0, b1);
            }
        }

        // ---- causal mask (diagonal tile only) ----
        if (kt == qt) {
            int qlo = w * 16 + lr;       // within-tile row == within-tile key space
            int qhi = qlo + 8;
            #pragma unroll
            for (int n = 0; n < 8; n++) {
                int key = n * 8 + 2 * lc;
                if (key     > qlo) s[n][0] = -1e30f;
                if (key + 1 > qlo) s[n][1] = -1e30f;
                if (key     > qhi) s[n][2] = -1e30f;
                if (key + 1 > qhi) s[n][3] = -1e30f;
            }
        }

        // ---- online softmax ----
        float rmx0 = -1e30f, rmx1 = -1e30f;
        #pragma unroll
        for (int n = 0; n < 8; n++) {
            rmx0 = fmaxf(rmx0, fmaxf(s[n][0], s[n][1]));
            rmx1 = fmaxf(rmx1, fmaxf(s[n][2], s[n][3]));
        }
        rmx0 = fmaxf(rmx0, __shfl_xor_sync(0xffffffffu, rmx0, 1));
        rmx0 = fmaxf(rmx0, __shfl_xor_sync(0xffffffffu, rmx0, 2));
        rmx1 = fmaxf(rmx1, __shfl_xor_sync(0xffffffffu, rmx1, 1));
        rmx1 = fmaxf(rmx1, __shfl_xor_sync(0xffffffffu, rmx1, 2));

        float mn0 = fmaxf(m0, rmx0);
        float mn1 = fmaxf(m1, rmx1);
        float corr0 = __expf(m0 - mn0);
        float corr1 = __expf(m1 - mn1);
        m0 = mn0; m1 = mn1;

        float ps0 = 0.f, ps1 = 0.f;
        #pragma unroll
        for (int n = 0; n < 8; n++) {
            s[n][0] = __expf(s[n][0] - mn0);
            s[n][1] = __expf(s[n][1] - mn0);
            s[n][2] = __expf(s[n][2] - mn1);
            s[n][3] = __expf(s[n][3] - mn1);
            ps0 += s[n][0] + s[n][1];
            ps1 += s[n][2] + s[n][3];
        }
        ps0 += __shfl_xor_sync(0xffffffffu, ps0, 1);
        ps0 += __shfl_xor_sync(0xffffffffu, ps0, 2);
        ps1 += __shfl_xor_sync(0xffffffffu, ps1, 1);
        ps1 += __shfl_xor_sync(0xffffffffu, ps1, 2);
        l0 = l0 * corr0 + ps0;
        l1 = l1 * corr1 + ps1;

        #pragma unroll
        for (int n = 0; n < 8; n++) {
            o[n][0] *= corr0; o[n][1] *= corr0;
            o[n][2] *= corr1; o[n][3] *= corr1;
        }

        // ---- PV: O += P * V (P in regs via key permutation) ----
        #pragma unroll
        for (int k = 0; k < 8; k++) {
            uint32_t a0 = tf32u(s[k][0]);
            uint32_t a1 = tf32u(s[k][2]);
            uint32_t a2 = tf32u(s[k][1]);
            uint32_t a3 = tf32u(s[k][3]);
            #pragma unroll
            for (int n = 0; n < 8; n++) {
                uint32_t b0 = Vsu[(k * 8 + 2 * lc)     * VSTR + n * 8 + lr];
                uint32_t b1 = Vsu[(k * 8 + 2 * lc + 1) * VSTR + n * 8 + lr];
                mma_tf32(o[n], a0, a1, a2, a3, b0, b1);
            }
        }
    }

    // ---- epilogue: normalize + store ----
    float2* Og = (float2*)(Og_ + base);
    {
        float inv0 = 1.0f / l0;
        float inv1 = 1.0f / l1;
        int grow = qt * QT + w * 16 + lr;
        #pragma unroll
        for (int n = 0; n < 8; n++) {
            Og[ grow      * 32 + n * 4 + lc] = make_float2(o[n][0] * inv0, o[n][1] * inv0);
            Og[(grow + 8) * 32 + n * 4 + lc] = make_float2(o[n][2] * inv1, o[n][3] * inv1);
        }
    }
}

extern "C" void kernel_launch(void* const* d_in, const int* in_sizes, int n_in,
                              void* d_out, int out_size) {
    const float* K = (const float*)d_in[0];
    const float* Q = (const float*)d_in[1];
    const float* V = (const float*)d_in[2];
    float* O = (float*)d_out;

    size_t smem = (size_t)(QT * QSTR + KT * KSTR + KT * VSTR) * sizeof(float);  // 52224 B
    cudaFuncSetAttribute(fa_tf32_kernel,
                         cudaFuncAttributeMaxDynamicSharedMemorySize, (int)smem);

    dim3 grid(SEQ / QT, 48);
    fa_tf32_kernel<<<grid, 128, (int)smem>>>(K, Q, V, O);
}